// round 13
// baseline (speedup 1.0000x reference)
#include <cuda_runtime.h>
#include <cuda_bf16.h>
#include <mma.h>
#include <cstdint>

using namespace nvcuda;

// Problem constants
#define B_   2
#define T_   4096
#define PD   256
#define E_   512
#define NH   8
#define HD   64
#define H3   1536
#define M_   (B_*T_)   // 8192

// Scratch (static device globals: no allocation allowed)
__device__ float g_x[(size_t)M_*E_];     // 16 MB
__device__ float g_qkv[(size_t)M_*H3];   // 48 MB
__device__ float g_att[(size_t)M_*E_];   // 16 MB

// ---------------------------------------------------------------------------
// Generic TF32 GEMM with bias:  C[M,N] = A[M,K](row) * B[K,N](row) + bias[N]
// (unchanged from R11 — attention is this round's target)
// ---------------------------------------------------------------------------
#define GBM 64
#define GBN 64
#define GBK 16
#define AKP 20
#define BNP 68

#define CVT_FRAG(f) do { _Pragma("unroll") \
    for (int _i = 0; _i < (f).num_elements; _i++) \
        (f).x[_i] = wmma::__float_to_tf32((f).x[_i]); } while (0)

__global__ __launch_bounds__(128) void gemm_bias_kernel(
    const float* __restrict__ A, const float* __restrict__ B,
    const float* __restrict__ bias, float* __restrict__ C,
    int M, int N, int K)
{
    __shared__ __align__(32) float As[GBM][AKP];
    __shared__ __align__(32) float Bs[GBK][BNP];
    __shared__ __align__(32) float Cs[GBM][GBN + 4];

    const int tid  = threadIdx.x;
    const int w    = tid >> 5;
    const int wr   = w >> 1;
    const int wc   = w & 1;
    const int row0 = blockIdx.y * GBM;
    const int col0 = blockIdx.x * GBN;

    wmma::fragment<wmma::accumulator, 16, 16, 8, float> acc[2][2];
#pragma unroll
    for (int i = 0; i < 2; i++)
#pragma unroll
        for (int j = 0; j < 2; j++)
            wmma::fill_fragment(acc[i][j], 0.0f);

    for (int k0 = 0; k0 < K; k0 += GBK) {
#pragma unroll
        for (int e = tid; e < GBM * GBK; e += 128) {
            int r = e >> 4, kk = e & 15;
            As[r][kk] = A[(size_t)(row0 + r) * K + k0 + kk];
        }
#pragma unroll
        for (int e = tid; e < GBK * GBN; e += 128) {
            int kk = e >> 6, n = e & 63;
            Bs[kk][n] = B[(size_t)(k0 + kk) * N + col0 + n];
        }
        __syncthreads();

#pragma unroll
        for (int ks = 0; ks < GBK; ks += 8) {
            wmma::fragment<wmma::matrix_a, 16, 16, 8, wmma::precision::tf32, wmma::row_major> af[2];
            wmma::fragment<wmma::matrix_b, 16, 16, 8, wmma::precision::tf32, wmma::row_major> bf[2];
            wmma::load_matrix_sync(af[0], &As[wr * 32][ks], AKP);
            wmma::load_matrix_sync(af[1], &As[wr * 32 + 16][ks], AKP);
            CVT_FRAG(af[0]); CVT_FRAG(af[1]);
            wmma::load_matrix_sync(bf[0], &Bs[ks][wc * 32], BNP);
            wmma::load_matrix_sync(bf[1], &Bs[ks][wc * 32 + 16], BNP);
            CVT_FRAG(bf[0]); CVT_FRAG(bf[1]);
#pragma unroll
            for (int i = 0; i < 2; i++)
#pragma unroll
                for (int j = 0; j < 2; j++)
                    wmma::mma_sync(acc[i][j], af[i], bf[j], acc[i][j]);
        }
        __syncthreads();
    }

#pragma unroll
    for (int i = 0; i < 2; i++)
#pragma unroll
        for (int j = 0; j < 2; j++)
            wmma::store_matrix_sync(&Cs[wr * 32 + i * 16][wc * 32 + j * 16],
                                    acc[i][j], GBN + 4, wmma::mem_row_major);
    __syncthreads();
#pragma unroll
    for (int e = tid; e < GBM * GBN; e += 128) {
        int r = e >> 6, n = e & 63;
        C[(size_t)(row0 + r) * N + col0 + n] = Cs[r][n] + bias[col0 + n];
    }
}

// ---------------------------------------------------------------------------
// Flash attention v2: register-resident S/O/m/l, raw mma.m16n8k8 tf32.
// Block: 4 warps (128 thr), q-tile 64 (16 rows/warp), kv-tile 64.
// Grid: (T/64, B*NH).
// ---------------------------------------------------------------------------
#define QT2  64
#define KT2  64
#define KLD  68   // K & P lead dim: bank = 4r+j -> conflict-free for row=t/4,col=t%4 pattern
#define VLD  72   // V lead dim:     bank = 8j+r -> conflict-free for row=t%4,col=t/4 pattern
#define PLD  68

#define ATT2_SMEM ((KT2*KLD + KT2*VLD + 4*16*PLD) * 4)   // 53248 B

__device__ __forceinline__ uint32_t f2tf32(float x) {
    uint32_t r;
    asm("cvt.rna.tf32.f32 %0, %1;" : "=r"(r) : "f"(x));
    return r;
}

__device__ __forceinline__ void mma_tf32(float c[4], const uint32_t a[4],
                                         uint32_t b0, uint32_t b1) {
    asm volatile(
        "mma.sync.aligned.m16n8k8.row.col.f32.tf32.tf32.f32 "
        "{%0,%1,%2,%3}, {%4,%5,%6,%7}, {%8,%9}, {%0,%1,%2,%3};"
        : "+f"(c[0]), "+f"(c[1]), "+f"(c[2]), "+f"(c[3])
        : "r"(a[0]), "r"(a[1]), "r"(a[2]), "r"(a[3]), "r"(b0), "r"(b1));
}

__global__ __launch_bounds__(128) void attn2_kernel(
    const float* __restrict__ qkv, float* __restrict__ att)
{
    extern __shared__ __align__(128) float sm2[];
    float* Ks = sm2;                    // KT2 x KLD (tf32 values)
    float* Vs = Ks + KT2 * KLD;         // KT2 x VLD (tf32 values)
    float* Ps = Vs + KT2 * VLD;         // 4 warps x 16 x PLD

    const int tid  = threadIdx.x;
    const int w    = tid >> 5;
    const int lane = tid & 31;
    const int qr   = lane >> 2;   // 0..7
    const int qc   = lane & 3;    // 0..3

    const int bh = blockIdx.y;
    const int b  = bh >> 3;
    const int h  = bh & 7;
    const int q0 = blockIdx.x * QT2;

    const float* qb = qkv + (size_t)b * T_ * H3 + (size_t)h * HD;
    const float* kb = qb + E_;
    const float* vb = qb + 2 * E_;

    // ---- Stage Q (scaled by 1/sqrt(d)) through Ks, build Q fragments ----
#pragma unroll
    for (int e = tid; e < QT2 * HD / 4; e += 128) {
        int r  = e >> 4;
        int c4 = (e & 15) << 2;
        float4 v = *(const float4*)(qb + (size_t)(q0 + r) * H3 + c4);
        v.x *= 0.125f; v.y *= 0.125f; v.z *= 0.125f; v.w *= 0.125f;
        *(float4*)(Ks + r * KLD + c4) = v;
    }
    __syncthreads();

    uint32_t qa[8][4];
    {
        const float* q00 = Ks + (w * 16 + qr) * KLD + qc;
#pragma unroll
        for (int ks = 0; ks < 8; ks++) {
            qa[ks][0] = f2tf32(q00[ks * 8]);
            qa[ks][1] = f2tf32(q00[8 * KLD + ks * 8]);
            qa[ks][2] = f2tf32(q00[ks * 8 + 4]);
            qa[ks][3] = f2tf32(q00[8 * KLD + ks * 8 + 4]);
        }
    }

    float oacc[8][4];
#pragma unroll
    for (int nt = 0; nt < 8; nt++)
#pragma unroll
        for (int i = 0; i < 4; i++) oacc[nt][i] = 0.0f;
    float m0 = -1e30f, m1 = -1e30f, l0 = 0.0f, l1 = 0.0f;

    float* Pw = Ps + w * 16 * PLD;

    for (int kt = 0; kt < T_; kt += KT2) {
        __syncthreads();   // all warps done reading Ks/Vs of previous tile

        // ---- Load K, V tiles (convert to tf32 once, at fill) ----
#pragma unroll
        for (int e = tid; e < KT2 * HD / 4; e += 128) {
            int r  = e >> 4;
            int c4 = (e & 15) << 2;
            const size_t gofs = (size_t)(kt + r) * H3 + c4;
            float4 kv = *(const float4*)(kb + gofs);
            kv.x = __uint_as_float(f2tf32(kv.x));
            kv.y = __uint_as_float(f2tf32(kv.y));
            kv.z = __uint_as_float(f2tf32(kv.z));
            kv.w = __uint_as_float(f2tf32(kv.w));
            *(float4*)(Ks + r * KLD + c4) = kv;
            float4 vv = *(const float4*)(vb + gofs);
            vv.x = __uint_as_float(f2tf32(vv.x));
            vv.y = __uint_as_float(f2tf32(vv.y));
            vv.z = __uint_as_float(f2tf32(vv.z));
            vv.w = __uint_as_float(f2tf32(vv.w));
            *(float4*)(Vs + r * VLD + c4) = vv;
        }
        __syncthreads();

        // ---- S = Q @ K^T (registers) ----
        float sacc[8][4];
#pragma unroll
        for (int nt = 0; nt < 8; nt++) {
            sacc[nt][0] = sacc[nt][1] = sacc[nt][2] = sacc[nt][3] = 0.0f;
            const float* kbase = Ks + (nt * 8 + qr) * KLD + qc;
#pragma unroll
            for (int ks = 0; ks < 8; ks++) {
                uint32_t b0 = __float_as_uint(kbase[ks * 8]);
                uint32_t b1 = __float_as_uint(kbase[ks * 8 + 4]);
                mma_tf32(sacc[nt], qa[ks], b0, b1);
            }
        }

        // ---- Online softmax in registers ----
        float tm0 = -1e30f, tm1 = -1e30f;
#pragma unroll
        for (int nt = 0; nt < 8; nt++) {
            tm0 = fmaxf(tm0, fmaxf(sacc[nt][0], sacc[nt][1]));
            tm1 = fmaxf(tm1, fmaxf(sacc[nt][2], sacc[nt][3]));
        }
        tm0 = fmaxf(tm0, __shfl_xor_sync(0xffffffffu, tm0, 1));
        tm0 = fmaxf(tm0, __shfl_xor_sync(0xffffffffu, tm0, 2));
        tm1 = fmaxf(tm1, __shfl_xor_sync(0xffffffffu, tm1, 1));
        tm1 = fmaxf(tm1, __shfl_xor_sync(0xffffffffu, tm1, 2));

        const float mn0 = fmaxf(m0, tm0);
        const float mn1 = fmaxf(m1, tm1);
        const float al0 = __expf(m0 - mn0);
        const float al1 = __expf(m1 - mn1);
        m0 = mn0; m1 = mn1;

        float s0 = 0.0f, s1 = 0.0f;
#pragma unroll
        for (int nt = 0; nt < 8; nt++) {
            float p0 = __expf(sacc[nt][0] - mn0);
            float p1 = __expf(sacc[nt][1] - mn0);
            float p2 = __expf(sacc[nt][2] - mn1);
            float p3 = __expf(sacc[nt][3] - mn1);
            s0 += p0 + p1;
            s1 += p2 + p3;
            // store P (tf32-rounded) to per-warp smem for PV A-frags
            float* pr = Pw + qr * PLD + nt * 8 + 2 * qc;
            *(float2*)pr = make_float2(__uint_as_float(f2tf32(p0)),
                                       __uint_as_float(f2tf32(p1)));
            *(float2*)(pr + 8 * PLD) = make_float2(__uint_as_float(f2tf32(p2)),
                                                   __uint_as_float(f2tf32(p3)));
        }
        s0 += __shfl_xor_sync(0xffffffffu, s0, 1);
        s0 += __shfl_xor_sync(0xffffffffu, s0, 2);
        s1 += __shfl_xor_sync(0xffffffffu, s1, 1);
        s1 += __shfl_xor_sync(0xffffffffu, s1, 2);
        l0 = l0 * al0 + s0;
        l1 = l1 * al1 + s1;

#pragma unroll
        for (int nt = 0; nt < 8; nt++) {
            oacc[nt][0] *= al0; oacc[nt][1] *= al0;
            oacc[nt][2] *= al1; oacc[nt][3] *= al1;
        }
        __syncwarp();   // P visible to the warp's fragment loads

        // ---- O += P @ V ----
#pragma unroll
        for (int ks = 0; ks < 8; ks++) {
            uint32_t pa[4];
            const float* pb = Pw + qr * PLD + ks * 8 + qc;
            pa[0] = __float_as_uint(pb[0]);
            pa[1] = __float_as_uint(pb[8 * PLD]);
            pa[2] = __float_as_uint(pb[4]);
            pa[3] = __float_as_uint(pb[8 * PLD + 4]);
            const float* vbase = Vs + (ks * 8 + qc) * VLD + qr;
#pragma unroll
            for (int nt = 0; nt < 8; nt++) {
                uint32_t b0 = __float_as_uint(vbase[nt * 8]);
                uint32_t b1 = __float_as_uint(vbase[4 * VLD + nt * 8]);
                mma_tf32(oacc[nt], pa, b0, b1);
            }
        }
    }

    // ---- Normalize and write out ----
    const float inv0 = 1.0f / l0;
    const float inv1 = 1.0f / l1;
    const size_t row0 = (size_t)(b * T_ + q0 + w * 16 + qr);
    float* o0 = att + row0 * E_ + h * HD + 2 * qc;
    float* o1 = o0 + 8 * E_;
#pragma unroll
    for (int nt = 0; nt < 8; nt++) {
        *(float2*)(o0 + nt * 8) = make_float2(oacc[nt][0] * inv0, oacc[nt][1] * inv0);
        *(float2*)(o1 + nt * 8) = make_float2(oacc[nt][2] * inv1, oacc[nt][3] * inv1);
    }
}

// ---------------------------------------------------------------------------
// Launch
// ---------------------------------------------------------------------------
extern "C" void kernel_launch(void* const* d_in, const int* in_sizes, int n_in,
                              void* d_out, int out_size)
{
    const float* prompt = (const float*)d_in[0];
    const float* Wp     = (const float*)d_in[1];
    const float* bp     = (const float*)d_in[2];
    const float* Wqkv   = (const float*)d_in[3];
    const float* bqkv   = (const float*)d_in[4];
    const float* Wo     = (const float*)d_in[5];
    const float* bo     = (const float*)d_in[6];
    float* out = (float*)d_out;

    float *x, *qkv, *att;
    cudaGetSymbolAddress((void**)&x,   g_x);
    cudaGetSymbolAddress((void**)&qkv, g_qkv);
    cudaGetSymbolAddress((void**)&att, g_att);

    cudaFuncSetAttribute(attn2_kernel,
                         cudaFuncAttributeMaxDynamicSharedMemorySize,
                         ATT2_SMEM);

    // 1) x = prompt @ Wp + bp          [8192,256]x[256,512]
    {
        dim3 g(E_ / GBN, M_ / GBM);
        gemm_bias_kernel<<<g, 128>>>(prompt, Wp, bp, x, M_, E_, PD);
    }
    // 2) qkv = x @ Wqkv + bqkv         [8192,512]x[512,1536]
    {
        dim3 g(H3 / GBN, M_ / GBM);
        gemm_bias_kernel<<<g, 128>>>(x, Wqkv, bqkv, qkv, M_, H3, E_);
    }
    // 3) attention (flash v2, register-resident)
    {
        dim3 g(T_ / QT2, B_ * NH);
        attn2_kernel<<<g, 128, ATT2_SMEM>>>(qkv, att);
    }
    // 4) out = att @ Wo + bo           [8192,512]x[512,256]
    {
        dim3 g(PD / GBN, M_ / GBM);
        gemm_bias_kernel<<<g, 128>>>(att, Wo, bo, out, M_, PD, E_);
    }
}

// round 14
// speedup vs baseline: 1.0006x; 1.0006x over previous
#include <cuda_runtime.h>
#include <cuda_bf16.h>
#include <mma.h>
#include <cstdint>

using namespace nvcuda;

// Problem constants
#define B_   2
#define T_   4096
#define PD   256
#define E_   512
#define NH   8
#define HD   64
#define H3   1536
#define M_   (B_*T_)   // 8192

// Scratch (static device globals: no allocation allowed)
__device__ float g_x[(size_t)M_*E_];     // 16 MB
__device__ float g_qkv[(size_t)M_*H3];   // 48 MB
__device__ float g_att[(size_t)M_*E_];   // 16 MB

// ---------------------------------------------------------------------------
// Generic TF32 GEMM with bias:  C[M,N] = A[M,K](row) * B[K,N](row) + bias[N]
// (unchanged from R11 — attention is this round's target)
// ---------------------------------------------------------------------------
#define GBM 64
#define GBN 64
#define GBK 16
#define AKP 20
#define BNP 68

#define CVT_FRAG(f) do { _Pragma("unroll") \
    for (int _i = 0; _i < (f).num_elements; _i++) \
        (f).x[_i] = wmma::__float_to_tf32((f).x[_i]); } while (0)

__global__ __launch_bounds__(128) void gemm_bias_kernel(
    const float* __restrict__ A, const float* __restrict__ B,
    const float* __restrict__ bias, float* __restrict__ C,
    int M, int N, int K)
{
    __shared__ __align__(32) float As[GBM][AKP];
    __shared__ __align__(32) float Bs[GBK][BNP];
    __shared__ __align__(32) float Cs[GBM][GBN + 4];

    const int tid  = threadIdx.x;
    const int w    = tid >> 5;
    const int wr   = w >> 1;
    const int wc   = w & 1;
    const int row0 = blockIdx.y * GBM;
    const int col0 = blockIdx.x * GBN;

    wmma::fragment<wmma::accumulator, 16, 16, 8, float> acc[2][2];
#pragma unroll
    for (int i = 0; i < 2; i++)
#pragma unroll
        for (int j = 0; j < 2; j++)
            wmma::fill_fragment(acc[i][j], 0.0f);

    for (int k0 = 0; k0 < K; k0 += GBK) {
#pragma unroll
        for (int e = tid; e < GBM * GBK; e += 128) {
            int r = e >> 4, kk = e & 15;
            As[r][kk] = A[(size_t)(row0 + r) * K + k0 + kk];
        }
#pragma unroll
        for (int e = tid; e < GBK * GBN; e += 128) {
            int kk = e >> 6, n = e & 63;
            Bs[kk][n] = B[(size_t)(k0 + kk) * N + col0 + n];
        }
        __syncthreads();

#pragma unroll
        for (int ks = 0; ks < GBK; ks += 8) {
            wmma::fragment<wmma::matrix_a, 16, 16, 8, wmma::precision::tf32, wmma::row_major> af[2];
            wmma::fragment<wmma::matrix_b, 16, 16, 8, wmma::precision::tf32, wmma::row_major> bf[2];
            wmma::load_matrix_sync(af[0], &As[wr * 32][ks], AKP);
            wmma::load_matrix_sync(af[1], &As[wr * 32 + 16][ks], AKP);
            CVT_FRAG(af[0]); CVT_FRAG(af[1]);
            wmma::load_matrix_sync(bf[0], &Bs[ks][wc * 32], BNP);
            wmma::load_matrix_sync(bf[1], &Bs[ks][wc * 32 + 16], BNP);
            CVT_FRAG(bf[0]); CVT_FRAG(bf[1]);
#pragma unroll
            for (int i = 0; i < 2; i++)
#pragma unroll
                for (int j = 0; j < 2; j++)
                    wmma::mma_sync(acc[i][j], af[i], bf[j], acc[i][j]);
        }
        __syncthreads();
    }

#pragma unroll
    for (int i = 0; i < 2; i++)
#pragma unroll
        for (int j = 0; j < 2; j++)
            wmma::store_matrix_sync(&Cs[wr * 32 + i * 16][wc * 32 + j * 16],
                                    acc[i][j], GBN + 4, wmma::mem_row_major);
    __syncthreads();
#pragma unroll
    for (int e = tid; e < GBM * GBN; e += 128) {
        int r = e >> 6, n = e & 63;
        C[(size_t)(row0 + r) * N + col0 + n] = Cs[r][n] + bias[col0 + n];
    }
}

// ---------------------------------------------------------------------------
// Flash attention v2: register-resident S/O/m/l, raw mma.m16n8k8 tf32.
// Block: 4 warps (128 thr), q-tile 64 (16 rows/warp), kv-tile 64.
// Grid: (T/64, B*NH).
// ---------------------------------------------------------------------------
#define QT2  64
#define KT2  64
#define KLD  68   // K & P lead dim: bank = 4r+j -> conflict-free for row=t/4,col=t%4 pattern
#define VLD  72   // V lead dim:     bank = 8j+r -> conflict-free for row=t%4,col=t/4 pattern
#define PLD  68

#define ATT2_SMEM ((KT2*KLD + KT2*VLD + 4*16*PLD) * 4)   // 53248 B

__device__ __forceinline__ uint32_t f2tf32(float x) {
    uint32_t r;
    asm("cvt.rna.tf32.f32 %0, %1;" : "=r"(r) : "f"(x));
    return r;
}

__device__ __forceinline__ void mma_tf32(float c[4], const uint32_t a[4],
                                         uint32_t b0, uint32_t b1) {
    asm volatile(
        "mma.sync.aligned.m16n8k8.row.col.f32.tf32.tf32.f32 "
        "{%0,%1,%2,%3}, {%4,%5,%6,%7}, {%8,%9}, {%0,%1,%2,%3};"
        : "+f"(c[0]), "+f"(c[1]), "+f"(c[2]), "+f"(c[3])
        : "r"(a[0]), "r"(a[1]), "r"(a[2]), "r"(a[3]), "r"(b0), "r"(b1));
}

__global__ __launch_bounds__(128) void attn2_kernel(
    const float* __restrict__ qkv, float* __restrict__ att)
{
    extern __shared__ __align__(128) float sm2[];
    float* Ks = sm2;                    // KT2 x KLD (tf32 values)
    float* Vs = Ks + KT2 * KLD;         // KT2 x VLD (tf32 values)
    float* Ps = Vs + KT2 * VLD;         // 4 warps x 16 x PLD

    const int tid  = threadIdx.x;
    const int w    = tid >> 5;
    const int lane = tid & 31;
    const int qr   = lane >> 2;   // 0..7
    const int qc   = lane & 3;    // 0..3

    const int bh = blockIdx.y;
    const int b  = bh >> 3;
    const int h  = bh & 7;
    const int q0 = blockIdx.x * QT2;

    const float* qb = qkv + (size_t)b * T_ * H3 + (size_t)h * HD;
    const float* kb = qb + E_;
    const float* vb = qb + 2 * E_;

    // ---- Stage Q (scaled by 1/sqrt(d)) through Ks, build Q fragments ----
#pragma unroll
    for (int e = tid; e < QT2 * HD / 4; e += 128) {
        int r  = e >> 4;
        int c4 = (e & 15) << 2;
        float4 v = *(const float4*)(qb + (size_t)(q0 + r) * H3 + c4);
        v.x *= 0.125f; v.y *= 0.125f; v.z *= 0.125f; v.w *= 0.125f;
        *(float4*)(Ks + r * KLD + c4) = v;
    }
    __syncthreads();

    uint32_t qa[8][4];
    {
        const float* q00 = Ks + (w * 16 + qr) * KLD + qc;
#pragma unroll
        for (int ks = 0; ks < 8; ks++) {
            qa[ks][0] = f2tf32(q00[ks * 8]);
            qa[ks][1] = f2tf32(q00[8 * KLD + ks * 8]);
            qa[ks][2] = f2tf32(q00[ks * 8 + 4]);
            qa[ks][3] = f2tf32(q00[8 * KLD + ks * 8 + 4]);
        }
    }

    float oacc[8][4];
#pragma unroll
    for (int nt = 0; nt < 8; nt++)
#pragma unroll
        for (int i = 0; i < 4; i++) oacc[nt][i] = 0.0f;
    float m0 = -1e30f, m1 = -1e30f, l0 = 0.0f, l1 = 0.0f;

    float* Pw = Ps + w * 16 * PLD;

    for (int kt = 0; kt < T_; kt += KT2) {
        __syncthreads();   // all warps done reading Ks/Vs of previous tile

        // ---- Load K, V tiles (convert to tf32 once, at fill) ----
#pragma unroll
        for (int e = tid; e < KT2 * HD / 4; e += 128) {
            int r  = e >> 4;
            int c4 = (e & 15) << 2;
            const size_t gofs = (size_t)(kt + r) * H3 + c4;
            float4 kv = *(const float4*)(kb + gofs);
            kv.x = __uint_as_float(f2tf32(kv.x));
            kv.y = __uint_as_float(f2tf32(kv.y));
            kv.z = __uint_as_float(f2tf32(kv.z));
            kv.w = __uint_as_float(f2tf32(kv.w));
            *(float4*)(Ks + r * KLD + c4) = kv;
            float4 vv = *(const float4*)(vb + gofs);
            vv.x = __uint_as_float(f2tf32(vv.x));
            vv.y = __uint_as_float(f2tf32(vv.y));
            vv.z = __uint_as_float(f2tf32(vv.z));
            vv.w = __uint_as_float(f2tf32(vv.w));
            *(float4*)(Vs + r * VLD + c4) = vv;
        }
        __syncthreads();

        // ---- S = Q @ K^T (registers) ----
        float sacc[8][4];
#pragma unroll
        for (int nt = 0; nt < 8; nt++) {
            sacc[nt][0] = sacc[nt][1] = sacc[nt][2] = sacc[nt][3] = 0.0f;
            const float* kbase = Ks + (nt * 8 + qr) * KLD + qc;
#pragma unroll
            for (int ks = 0; ks < 8; ks++) {
                uint32_t b0 = __float_as_uint(kbase[ks * 8]);
                uint32_t b1 = __float_as_uint(kbase[ks * 8 + 4]);
                mma_tf32(sacc[nt], qa[ks], b0, b1);
            }
        }

        // ---- Online softmax in registers ----
        float tm0 = -1e30f, tm1 = -1e30f;
#pragma unroll
        for (int nt = 0; nt < 8; nt++) {
            tm0 = fmaxf(tm0, fmaxf(sacc[nt][0], sacc[nt][1]));
            tm1 = fmaxf(tm1, fmaxf(sacc[nt][2], sacc[nt][3]));
        }
        tm0 = fmaxf(tm0, __shfl_xor_sync(0xffffffffu, tm0, 1));
        tm0 = fmaxf(tm0, __shfl_xor_sync(0xffffffffu, tm0, 2));
        tm1 = fmaxf(tm1, __shfl_xor_sync(0xffffffffu, tm1, 1));
        tm1 = fmaxf(tm1, __shfl_xor_sync(0xffffffffu, tm1, 2));

        const float mn0 = fmaxf(m0, tm0);
        const float mn1 = fmaxf(m1, tm1);
        const float al0 = __expf(m0 - mn0);
        const float al1 = __expf(m1 - mn1);
        m0 = mn0; m1 = mn1;

        float s0 = 0.0f, s1 = 0.0f;
#pragma unroll
        for (int nt = 0; nt < 8; nt++) {
            float p0 = __expf(sacc[nt][0] - mn0);
            float p1 = __expf(sacc[nt][1] - mn0);
            float p2 = __expf(sacc[nt][2] - mn1);
            float p3 = __expf(sacc[nt][3] - mn1);
            s0 += p0 + p1;
            s1 += p2 + p3;
            // store P (tf32-rounded) to per-warp smem for PV A-frags
            float* pr = Pw + qr * PLD + nt * 8 + 2 * qc;
            *(float2*)pr = make_float2(__uint_as_float(f2tf32(p0)),
                                       __uint_as_float(f2tf32(p1)));
            *(float2*)(pr + 8 * PLD) = make_float2(__uint_as_float(f2tf32(p2)),
                                                   __uint_as_float(f2tf32(p3)));
        }
        s0 += __shfl_xor_sync(0xffffffffu, s0, 1);
        s0 += __shfl_xor_sync(0xffffffffu, s0, 2);
        s1 += __shfl_xor_sync(0xffffffffu, s1, 1);
        s1 += __shfl_xor_sync(0xffffffffu, s1, 2);
        l0 = l0 * al0 + s0;
        l1 = l1 * al1 + s1;

#pragma unroll
        for (int nt = 0; nt < 8; nt++) {
            oacc[nt][0] *= al0; oacc[nt][1] *= al0;
            oacc[nt][2] *= al1; oacc[nt][3] *= al1;
        }
        __syncwarp();   // P visible to the warp's fragment loads

        // ---- O += P @ V ----
#pragma unroll
        for (int ks = 0; ks < 8; ks++) {
            uint32_t pa[4];
            const float* pb = Pw + qr * PLD + ks * 8 + qc;
            pa[0] = __float_as_uint(pb[0]);
            pa[1] = __float_as_uint(pb[8 * PLD]);
            pa[2] = __float_as_uint(pb[4]);
            pa[3] = __float_as_uint(pb[8 * PLD + 4]);
            const float* vbase = Vs + (ks * 8 + qc) * VLD + qr;
#pragma unroll
            for (int nt = 0; nt < 8; nt++) {
                uint32_t b0 = __float_as_uint(vbase[nt * 8]);
                uint32_t b1 = __float_as_uint(vbase[4 * VLD + nt * 8]);
                mma_tf32(oacc[nt], pa, b0, b1);
            }
        }
    }

    // ---- Normalize and write out ----
    const float inv0 = 1.0f / l0;
    const float inv1 = 1.0f / l1;
    const size_t row0 = (size_t)(b * T_ + q0 + w * 16 + qr);
    float* o0 = att + row0 * E_ + h * HD + 2 * qc;
    float* o1 = o0 + 8 * E_;
#pragma unroll
    for (int nt = 0; nt < 8; nt++) {
        *(float2*)(o0 + nt * 8) = make_float2(oacc[nt][0] * inv0, oacc[nt][1] * inv0);
        *(float2*)(o1 + nt * 8) = make_float2(oacc[nt][2] * inv1, oacc[nt][3] * inv1);
    }
}

// ---------------------------------------------------------------------------
// Launch
// ---------------------------------------------------------------------------
extern "C" void kernel_launch(void* const* d_in, const int* in_sizes, int n_in,
                              void* d_out, int out_size)
{
    const float* prompt = (const float*)d_in[0];
    const float* Wp     = (const float*)d_in[1];
    const float* bp     = (const float*)d_in[2];
    const float* Wqkv   = (const float*)d_in[3];
    const float* bqkv   = (const float*)d_in[4];
    const float* Wo     = (const float*)d_in[5];
    const float* bo     = (const float*)d_in[6];
    float* out = (float*)d_out;

    float *x, *qkv, *att;
    cudaGetSymbolAddress((void**)&x,   g_x);
    cudaGetSymbolAddress((void**)&qkv, g_qkv);
    cudaGetSymbolAddress((void**)&att, g_att);

    cudaFuncSetAttribute(attn2_kernel,
                         cudaFuncAttributeMaxDynamicSharedMemorySize,
                         ATT2_SMEM);

    // 1) x = prompt @ Wp + bp          [8192,256]x[256,512]
    {
        dim3 g(E_ / GBN, M_ / GBM);
        gemm_bias_kernel<<<g, 128>>>(prompt, Wp, bp, x, M_, E_, PD);
    }
    // 2) qkv = x @ Wqkv + bqkv         [8192,512]x[512,1536]
    {
        dim3 g(H3 / GBN, M_ / GBM);
        gemm_bias_kernel<<<g, 128>>>(x, Wqkv, bqkv, qkv, M_, H3, E_);
    }
    // 3) attention (flash v2, register-resident)
    {
        dim3 g(T_ / QT2, B_ * NH);
        attn2_kernel<<<g, 128, ATT2_SMEM>>>(qkv, att);
    }
    // 4) out = att @ Wo + bo           [8192,512]x[512,256]
    {
        dim3 g(PD / GBN, M_ / GBM);
        gemm_bias_kernel<<<g, 128>>>(att, Wo, bo, out, M_, PD, E_);
    }
}